// round 1
// baseline (speedup 1.0000x reference)
#include <cuda_runtime.h>
#include <cstdint>

#define B_SZ   1024
#define T_SZ   16
#define IN_DIM 2048
#define DIM    1024
#define NACT   64

// ---------------- scratch (no allocations allowed) ----------------
__device__ float g_pavg[B_SZ * IN_DIM];     // 8 MB
__device__ float g_eavg[B_SZ * IN_DIM];     // 8 MB
__device__ float g_pembed[B_SZ * DIM];      // 4 MB
__device__ int   g_counts[NACT];
__device__ int   g_cursor[NACT];
__device__ int   g_order[B_SZ];

// ---------------- helpers ----------------
__device__ __forceinline__ uint32_t f2tf32(float x) {
    uint32_t r;
    asm("cvt.rna.tf32.f32 %0, %1;" : "=r"(r) : "f"(x));
    return r;
}

__device__ __forceinline__ void mma_tf32(float c[4], const uint32_t a[4], const uint32_t b[2]) {
    asm volatile(
        "mma.sync.aligned.m16n8k8.row.col.f32.tf32.tf32.f32 "
        "{%0,%1,%2,%3}, {%4,%5,%6,%7}, {%8,%9}, {%0,%1,%2,%3};"
        : "+f"(c[0]), "+f"(c[1]), "+f"(c[2]), "+f"(c[3])
        : "r"(a[0]), "r"(a[1]), "r"(a[2]), "r"(a[3]), "r"(b[0]), "r"(b[1]));
}

// ---------------- grouping by action ----------------
__global__ void zero_counts_k() { g_counts[threadIdx.x] = 0; }

__global__ void count_k(const int* __restrict__ act) {
    int b = blockIdx.x * 256 + threadIdx.x;
    atomicAdd(&g_counts[act[b]], 1);
}

__global__ void scan_k() {
    __shared__ int s[NACT];
    s[threadIdx.x] = g_counts[threadIdx.x];
    __syncthreads();
    if (threadIdx.x == 0) {
        int run = 0;
        for (int i = 0; i < NACT; i++) { int c = s[i]; s[i] = run; run += c; }
    }
    __syncthreads();
    g_cursor[threadIdx.x] = s[threadIdx.x];
}

__global__ void scatter_k(const int* __restrict__ act) {
    int b = blockIdx.x * 256 + threadIdx.x;
    int a = act[b];
    int pos = atomicAdd(&g_cursor[a], 1);
    g_order[pos] = b;
}
// after scatter: g_cursor[a] = group_end(a); group_start = g_cursor[a] - g_counts[a]

// ---------------- time-mean ----------------
__global__ void mean_kernel(const float* __restrict__ pre, const float* __restrict__ eff) {
    int idx = blockIdx.x * blockDim.x + threadIdx.x;         // over B*IN
    const float* src = blockIdx.y ? eff : pre;
    float*       dst = blockIdx.y ? g_eavg : g_pavg;
    int b = idx >> 11;            // / IN_DIM
    int k = idx & (IN_DIM - 1);
    const float* p = src + (size_t)b * T_SZ * IN_DIM + k;
    float s = 0.f;
#pragma unroll
    for (int t = 0; t < T_SZ; t++) s += p[(size_t)t * IN_DIM];
    dst[idx] = s * (1.0f / T_SZ);
}

// ---------------- embedding GEMM: C[1024x1024] = A[1024x2048] @ W^T + bias ----------------
#define G1_BM 128
#define G1_BN 64
#define G1_BK 32
#define SPAD  36

__global__ __launch_bounds__(256) void embed_gemm(
    const float* __restrict__ Wp, const float* __restrict__ bp,
    const float* __restrict__ We, const float* __restrict__ be,
    float* __restrict__ out_e)
{
    __shared__ uint32_t As[G1_BM][SPAD];
    __shared__ uint32_t Bs[G1_BN][SPAD];

    const float *A, *W, *bias;
    float* out;
    if (blockIdx.z == 0) { A = g_pavg; W = Wp; bias = bp; out = g_pembed; }
    else                 { A = g_eavg; W = We; bias = be; out = out_e;   }

    const int m0 = blockIdx.y * G1_BM;
    const int n0 = blockIdx.x * G1_BN;
    const int tid  = threadIdx.x;
    const int lane = tid & 31;
    const int warp = tid >> 5;
    const int wm = (warp >> 1) * 32;   // 4 warps along M
    const int wn = (warp & 1) * 32;    // 2 warps along N

    float acc[2][4][4];
#pragma unroll
    for (int i = 0; i < 2; i++)
#pragma unroll
        for (int j = 0; j < 4; j++)
#pragma unroll
            for (int r = 0; r < 4; r++) acc[i][j][r] = 0.f;

    for (int k0 = 0; k0 < IN_DIM; k0 += G1_BK) {
        // load A tile 128x32
#pragma unroll
        for (int i = 0; i < 4; i++) {
            int idx = tid + i * 256;
            int r = idx >> 3, c = (idx & 7) * 4;
            float4 v = *(const float4*)(A + (size_t)(m0 + r) * IN_DIM + k0 + c);
            As[r][c]     = f2tf32(v.x);
            As[r][c + 1] = f2tf32(v.y);
            As[r][c + 2] = f2tf32(v.z);
            As[r][c + 3] = f2tf32(v.w);
        }
        // load W tile 64x32
#pragma unroll
        for (int i = 0; i < 2; i++) {
            int idx = tid + i * 256;
            int r = idx >> 3, c = (idx & 7) * 4;
            float4 v = *(const float4*)(W + (size_t)(n0 + r) * IN_DIM + k0 + c);
            Bs[r][c]     = f2tf32(v.x);
            Bs[r][c + 1] = f2tf32(v.y);
            Bs[r][c + 2] = f2tf32(v.z);
            Bs[r][c + 3] = f2tf32(v.w);
        }
        __syncthreads();

#pragma unroll
        for (int kk = 0; kk < G1_BK; kk += 8) {
            uint32_t af[2][4], bf[4][2];
#pragma unroll
            for (int ms = 0; ms < 2; ms++) {
                int r  = wm + ms * 16 + (lane >> 2);
                int cA = kk + (lane & 3);
                af[ms][0] = As[r][cA];
                af[ms][1] = As[r + 8][cA];
                af[ms][2] = As[r][cA + 4];
                af[ms][3] = As[r + 8][cA + 4];
            }
#pragma unroll
            for (int ns = 0; ns < 4; ns++) {
                int n  = wn + ns * 8 + (lane >> 2);
                int ck = kk + (lane & 3);
                bf[ns][0] = Bs[n][ck];
                bf[ns][1] = Bs[n][ck + 4];
            }
#pragma unroll
            for (int ms = 0; ms < 2; ms++)
#pragma unroll
                for (int ns = 0; ns < 4; ns++)
                    mma_tf32(acc[ms][ns], af[ms], bf[ns]);
        }
        __syncthreads();
    }

    // epilogue: + bias, write fp32
#pragma unroll
    for (int ns = 0; ns < 4; ns++) {
        int c0 = n0 + wn + ns * 8 + 2 * (lane & 3);
        float b0v = bias[c0];
        float b1v = bias[c0 + 1];
#pragma unroll
        for (int ms = 0; ms < 2; ms++) {
            int r0 = m0 + wm + ms * 16 + (lane >> 2);
            float2 lo = make_float2(acc[ms][ns][0] + b0v, acc[ms][ns][1] + b1v);
            float2 hi = make_float2(acc[ms][ns][2] + b0v, acc[ms][ns][3] + b1v);
            *(float2*)(out + (size_t)r0 * DIM + c0)       = lo;
            *(float2*)(out + (size_t)(r0 + 8) * DIM + c0) = hi;
        }
    }
}

// ---------------- grouped transform: p_t[b,i] = sum_j Wt[a_b][i][j] * p_embed[b][j] ----------------
#define T_BM 32    // batch chunk
#define T_BN 128   // output dims per block
#define T_BK 32

__global__ __launch_bounds__(256) void trans_gemm(const float* __restrict__ Wt,
                                                  float* __restrict__ out)
{
    const int a   = blockIdx.y;
    const int cnt = g_counts[a];
    const int chunk = blockIdx.z;
    if (chunk * T_BM >= cnt) return;

    const int start  = g_cursor[a] - cnt + chunk * T_BM;
    const int nvalid = min(T_BM, cnt - chunk * T_BM);

    __shared__ int      s_ord[T_BM];
    __shared__ uint32_t As[T_BM][SPAD];
    __shared__ uint32_t Bs[T_BN][SPAD];

    const int tid  = threadIdx.x;
    const int lane = tid & 31;
    const int warp = tid >> 5;
    const int wm = (warp >> 2) * 16;   // 2 warp-rows over 32 batches
    const int wn = (warp & 3) * 32;    // 4 warp-cols over 128 dims
    const int i0 = blockIdx.x * T_BN;

    if (tid < T_BM) s_ord[tid] = (tid < nvalid) ? g_order[start + tid] : -1;
    __syncthreads();

    const float* Wa = Wt + (size_t)a * DIM * DIM;

    float acc[4][4];
#pragma unroll
    for (int j = 0; j < 4; j++)
#pragma unroll
        for (int r = 0; r < 4; r++) acc[j][r] = 0.f;

    for (int k0 = 0; k0 < DIM; k0 += T_BK) {
        // A: gathered p_embed rows, 32x32 -> one float4 per thread
        {
            int r = tid >> 3, c = (tid & 7) * 4;
            int b = s_ord[r];
            float4 v = (b >= 0) ? *(const float4*)(g_pembed + (size_t)b * DIM + k0 + c)
                                : make_float4(0.f, 0.f, 0.f, 0.f);
            As[r][c]     = f2tf32(v.x);
            As[r][c + 1] = f2tf32(v.y);
            As[r][c + 2] = f2tf32(v.z);
            As[r][c + 3] = f2tf32(v.w);
        }
        // W tile 128x32 -> four float4 per thread
#pragma unroll
        for (int i = 0; i < 4; i++) {
            int idx = tid + i * 256;
            int r = idx >> 3, c = (idx & 7) * 4;
            float4 v = *(const float4*)(Wa + (size_t)(i0 + r) * DIM + k0 + c);
            Bs[r][c]     = f2tf32(v.x);
            Bs[r][c + 1] = f2tf32(v.y);
            Bs[r][c + 2] = f2tf32(v.z);
            Bs[r][c + 3] = f2tf32(v.w);
        }
        __syncthreads();

#pragma unroll
        for (int kk = 0; kk < T_BK; kk += 8) {
            uint32_t af[4], bf[4][2];
            {
                int r  = wm + (lane >> 2);
                int cA = kk + (lane & 3);
                af[0] = As[r][cA];
                af[1] = As[r + 8][cA];
                af[2] = As[r][cA + 4];
                af[3] = As[r + 8][cA + 4];
            }
#pragma unroll
            for (int ns = 0; ns < 4; ns++) {
                int n  = wn + ns * 8 + (lane >> 2);
                int ck = kk + (lane & 3);
                bf[ns][0] = Bs[n][ck];
                bf[ns][1] = Bs[n][ck + 4];
            }
#pragma unroll
            for (int ns = 0; ns < 4; ns++)
                mma_tf32(acc[ns], af, bf[ns]);
        }
        __syncthreads();
    }

    // epilogue: scatter to out[b*DIM + i]
    const int rA = wm + (lane >> 2);
    const int b0 = s_ord[rA];
    const int b1 = s_ord[rA + 8];
#pragma unroll
    for (int ns = 0; ns < 4; ns++) {
        int c0 = i0 + wn + ns * 8 + 2 * (lane & 3);
        if (b0 >= 0)
            *(float2*)(out + (size_t)b0 * DIM + c0) = make_float2(acc[ns][0], acc[ns][1]);
        if (b1 >= 0)
            *(float2*)(out + (size_t)b1 * DIM + c0) = make_float2(acc[ns][2], acc[ns][3]);
    }
}

// ---------------- launch ----------------
extern "C" void kernel_launch(void* const* d_in, const int* in_sizes, int n_in,
                              void* d_out, int out_size)
{
    const float* pre = (const float*)d_in[0];
    const float* eff = (const float*)d_in[1];
    const int*   act = (const int*)d_in[2];
    const float* Wp  = (const float*)d_in[3];
    const float* bp  = (const float*)d_in[4];
    const float* We  = (const float*)d_in[5];
    const float* be  = (const float*)d_in[6];
    const float* Wt  = (const float*)d_in[7];

    float* out   = (float*)d_out;              // p_transformed: (B,1,DIM,1) = B*DIM floats
    float* out_e = out + (size_t)B_SZ * DIM;   // e_embed: (B,DIM)

    zero_counts_k<<<1, NACT>>>();
    count_k<<<B_SZ / 256, 256>>>(act);
    scan_k<<<1, NACT>>>();
    scatter_k<<<B_SZ / 256, 256>>>(act);

    mean_kernel<<<dim3(B_SZ * IN_DIM / 256, 2), 256>>>(pre, eff);

    embed_gemm<<<dim3(DIM / G1_BN, DIM / G1_BM, 2), 256>>>(Wp, bp, We, be, out_e);

    trans_gemm<<<dim3(DIM / T_BN, NACT, B_SZ / T_BM), 256>>>(Wt, out);
}

// round 2
// speedup vs baseline: 1.4906x; 1.4906x over previous
#include <cuda_runtime.h>
#include <cstdint>

#define B_SZ   1024
#define T_SZ   16
#define IN_DIM 2048
#define DIM    1024
#define NACT   64

// ---------------- scratch (no allocations allowed) ----------------
__device__ float g_pavg[B_SZ * IN_DIM];     // 8 MB
__device__ float g_eavg[B_SZ * IN_DIM];     // 8 MB
__device__ float g_pembed[B_SZ * DIM];      // 4 MB
__device__ int   g_counts[NACT];
__device__ int   g_cursor[NACT];            // group END after group_k
__device__ int   g_order[B_SZ];

// ---------------- helpers ----------------
__device__ __forceinline__ uint32_t f2tf32(float x) {
    uint32_t r;
    asm("cvt.rna.tf32.f32 %0, %1;" : "=r"(r) : "f"(x));
    return r;
}

__device__ __forceinline__ void mma_tf32(float c[4], const uint32_t a[4], const uint32_t b[2]) {
    asm volatile(
        "mma.sync.aligned.m16n8k8.row.col.f32.tf32.tf32.f32 "
        "{%0,%1,%2,%3}, {%4,%5,%6,%7}, {%8,%9}, {%0,%1,%2,%3};"
        : "+f"(c[0]), "+f"(c[1]), "+f"(c[2]), "+f"(c[3])
        : "r"(a[0]), "r"(a[1]), "r"(a[2]), "r"(a[3]), "r"(b[0]), "r"(b[1]));
}

__device__ __forceinline__ void cpa16(float* dst, const float* src, uint32_t src_sz) {
    uint32_t d = (uint32_t)__cvta_generic_to_shared(dst);
    asm volatile("cp.async.ca.shared.global [%0], [%1], 16, %2;"
                 :: "r"(d), "l"(src), "r"(src_sz));
}
__device__ __forceinline__ void cpa_commit() { asm volatile("cp.async.commit_group;"); }
__device__ __forceinline__ void cpa_wait0()  { asm volatile("cp.async.wait_group 0;"); }

// ---------------- fused grouping: count + scan + scatter in ONE block ----------------
__global__ void group_k(const int* __restrict__ act) {
    __shared__ int s_cnt[NACT];
    __shared__ int s_base[NACT];
    const int tid = threadIdx.x;           // 1024 threads, one per batch
    if (tid < NACT) s_cnt[tid] = 0;
    __syncthreads();
    const int a = act[tid];
    atomicAdd(&s_cnt[a], 1);
    __syncthreads();
    if (tid == 0) {
        int run = 0;
        for (int i = 0; i < NACT; i++) { int c = s_cnt[i]; s_base[i] = run; run += c; }
    }
    __syncthreads();
    int pos = atomicAdd(&s_base[a], 1);
    g_order[pos] = tid;
    __syncthreads();
    if (tid < NACT) {
        g_counts[tid] = s_cnt[tid];
        g_cursor[tid] = s_base[tid];       // = group end
    }
}

// ---------------- time-mean (float4, MLP=16) ----------------
__global__ void mean_kernel(const float* __restrict__ pre, const float* __restrict__ eff) {
    const int idx = blockIdx.x * 256 + threadIdx.x;   // over B*IN/4
    const float4* src = (const float4*)(blockIdx.y ? eff : pre);
    float4*       dst = (float4*)(blockIdx.y ? g_eavg : g_pavg);
    const int b  = idx >> 9;               // / (IN_DIM/4)
    const int k4 = idx & 511;
    const float4* p = src + (size_t)b * T_SZ * (IN_DIM / 4) + k4;
    float4 s = make_float4(0.f, 0.f, 0.f, 0.f);
#pragma unroll
    for (int t = 0; t < T_SZ; t++) {
        float4 v = p[(size_t)t * (IN_DIM / 4)];
        s.x += v.x; s.y += v.y; s.z += v.z; s.w += v.w;
    }
    const float inv = 1.0f / T_SZ;
    dst[idx] = make_float4(s.x * inv, s.y * inv, s.z * inv, s.w * inv);
}

// ---------------- embedding GEMM: C[1024x1024] = A[1024x2048] @ W^T + bias ----------------
// 128x128 tile, BK=32, cp.async double-buffered, 8 warps (2M x 4N), warp tile 64x32
#define G1_BM 128
#define G1_BN 128
#define G1_BK 32
#define SPAD  36
#define G1_SMEM (4 * 128 * SPAD * 4)   // 2 bufs * (As 128x36 + Bs 128x36) floats

__global__ __launch_bounds__(256) void embed_gemm(
    const float* __restrict__ Wp, const float* __restrict__ bp,
    const float* __restrict__ We, const float* __restrict__ be,
    float* __restrict__ out_e)
{
    extern __shared__ float sm[];
    float* AsBase = sm;                       // [2][128][36]
    float* BsBase = sm + 2 * 128 * SPAD;      // [2][128][36]

    const float *A, *W, *bias;
    float* out;
    if (blockIdx.z == 0) { A = g_pavg; W = Wp; bias = bp; out = g_pembed; }
    else                 { A = g_eavg; W = We; bias = be; out = out_e;   }

    const int m0 = blockIdx.y * G1_BM;
    const int n0 = blockIdx.x * G1_BN;
    const int tid  = threadIdx.x;
    const int lane = tid & 31;
    const int warp = tid >> 5;
    const int wm = (warp >> 2) * 64;   // 2 warp-rows over 128 M
    const int wn = (warp & 3) * 32;    // 4 warp-cols over 128 N

    const int lr = tid >> 3;           // load row (within 128-row tile, 4 passes)
    const int lc = (tid & 7) * 4;      // load col (floats)

    float acc[4][4][4];
#pragma unroll
    for (int i = 0; i < 4; i++)
#pragma unroll
        for (int j = 0; j < 4; j++)
#pragma unroll
            for (int r = 0; r < 4; r++) acc[i][j][r] = 0.f;

    // prologue: stage 0
    {
        float* Ab = AsBase;
        float* Bb = BsBase;
#pragma unroll
        for (int i = 0; i < 4; i++) {
            int r = lr + i * 32;
            cpa16(&Ab[r * SPAD + lc], A + (size_t)(m0 + r) * IN_DIM + lc, 16);
            cpa16(&Bb[r * SPAD + lc], W + (size_t)(n0 + r) * IN_DIM + lc, 16);
        }
        cpa_commit();
    }

    const int NITER = IN_DIM / G1_BK;  // 64
    for (int it = 0; it < NITER; ++it) {
        cpa_wait0();
        __syncthreads();

        if (it + 1 < NITER) {
            const int k0 = (it + 1) * G1_BK;
            float* Ab = AsBase + ((it + 1) & 1) * 128 * SPAD;
            float* Bb = BsBase + ((it + 1) & 1) * 128 * SPAD;
#pragma unroll
            for (int i = 0; i < 4; i++) {
                int r = lr + i * 32;
                cpa16(&Ab[r * SPAD + lc], A + (size_t)(m0 + r) * IN_DIM + k0 + lc, 16);
                cpa16(&Bb[r * SPAD + lc], W + (size_t)(n0 + r) * IN_DIM + k0 + lc, 16);
            }
            cpa_commit();
        }

        const float* Ab = AsBase + (it & 1) * 128 * SPAD;
        const float* Bb = BsBase + (it & 1) * 128 * SPAD;

#pragma unroll
        for (int kk = 0; kk < G1_BK; kk += 8) {
            uint32_t af[4][4], bf[4][2];
#pragma unroll
            for (int ms = 0; ms < 4; ms++) {
                int r  = wm + ms * 16 + (lane >> 2);
                int cA = kk + (lane & 3);
                af[ms][0] = f2tf32(Ab[r * SPAD + cA]);
                af[ms][1] = f2tf32(Ab[(r + 8) * SPAD + cA]);
                af[ms][2] = f2tf32(Ab[r * SPAD + cA + 4]);
                af[ms][3] = f2tf32(Ab[(r + 8) * SPAD + cA + 4]);
            }
#pragma unroll
            for (int ns = 0; ns < 4; ns++) {
                int n  = wn + ns * 8 + (lane >> 2);
                int ck = kk + (lane & 3);
                bf[ns][0] = f2tf32(Bb[n * SPAD + ck]);
                bf[ns][1] = f2tf32(Bb[n * SPAD + ck + 4]);
            }
#pragma unroll
            for (int ms = 0; ms < 4; ms++)
#pragma unroll
                for (int ns = 0; ns < 4; ns++)
                    mma_tf32(acc[ms][ns], af[ms], bf[ns]);
        }
        __syncthreads();
    }

    // epilogue: + bias
#pragma unroll
    for (int ns = 0; ns < 4; ns++) {
        int c0 = n0 + wn + ns * 8 + 2 * (lane & 3);
        float b0v = bias[c0];
        float b1v = bias[c0 + 1];
#pragma unroll
        for (int ms = 0; ms < 4; ms++) {
            int r0 = m0 + wm + ms * 16 + (lane >> 2);
            *(float2*)(out + (size_t)r0 * DIM + c0) =
                make_float2(acc[ms][ns][0] + b0v, acc[ms][ns][1] + b1v);
            *(float2*)(out + (size_t)(r0 + 8) * DIM + c0) =
                make_float2(acc[ms][ns][2] + b0v, acc[ms][ns][3] + b1v);
        }
    }
}

// ---------------- grouped transform: p_t[b,i] = sum_j Wt[a_b][i][j] * p_embed[b][j] ----------------
#define T_BM 32
#define T_BN 128
#define T_BK 32

__global__ __launch_bounds__(256) void trans_gemm(const float* __restrict__ Wt,
                                                  float* __restrict__ out)
{
    const int a     = blockIdx.y;
    const int cnt   = g_counts[a];
    const int chunk = blockIdx.z;
    if (chunk * T_BM >= cnt) return;

    const int start  = g_cursor[a] - cnt + chunk * T_BM;
    const int nvalid = min(T_BM, cnt - chunk * T_BM);

    __shared__ int   s_ord[T_BM];
    __shared__ float As[2][T_BM][SPAD];
    __shared__ float Bs[2][T_BN][SPAD];

    const int tid  = threadIdx.x;
    const int lane = tid & 31;
    const int warp = tid >> 5;
    const int wm = (warp >> 2) * 16;   // 2 warp-rows over 32 batches
    const int wn = (warp & 3) * 32;    // 4 warp-cols over 128 dims
    const int i0 = blockIdx.x * T_BN;

    if (tid < T_BM) s_ord[tid] = (tid < nvalid) ? g_order[start + tid] : -1;
    __syncthreads();

    const float* Wa = Wt + (size_t)a * DIM * DIM;

    const int lrA = tid >> 3;          // 0..31
    const int lc  = (tid & 7) * 4;
    const int bA  = s_ord[lrA];
    const float* srcA0 = (bA >= 0) ? g_pembed + (size_t)bA * DIM + lc : g_pembed;
    const uint32_t szA = (bA >= 0) ? 16u : 0u;

    float acc[4][4];
#pragma unroll
    for (int j = 0; j < 4; j++)
#pragma unroll
        for (int r = 0; r < 4; r++) acc[j][r] = 0.f;

    // prologue
    {
        cpa16(&As[0][lrA][lc], srcA0, szA);
#pragma unroll
        for (int i = 0; i < 4; i++) {
            int r = lrA + i * 32;
            cpa16(&Bs[0][r][lc], Wa + (size_t)(i0 + r) * DIM + lc, 16);
        }
        cpa_commit();
    }

    const int NITER = DIM / T_BK;  // 32
    for (int it = 0; it < NITER; ++it) {
        cpa_wait0();
        __syncthreads();

        if (it + 1 < NITER) {
            const int k0 = (it + 1) * T_BK;
            const int nb = (it + 1) & 1;
            cpa16(&As[nb][lrA][lc], srcA0 + (szA ? k0 : 0), szA);
#pragma unroll
            for (int i = 0; i < 4; i++) {
                int r = lrA + i * 32;
                cpa16(&Bs[nb][r][lc], Wa + (size_t)(i0 + r) * DIM + k0 + lc, 16);
            }
            cpa_commit();
        }

        const int buf = it & 1;
#pragma unroll
        for (int kk = 0; kk < T_BK; kk += 8) {
            uint32_t af[4], bf[4][2];
            {
                int r  = wm + (lane >> 2);
                int cA = kk + (lane & 3);
                af[0] = f2tf32(As[buf][r][cA]);
                af[1] = f2tf32(As[buf][r + 8][cA]);
                af[2] = f2tf32(As[buf][r][cA + 4]);
                af[3] = f2tf32(As[buf][r + 8][cA + 4]);
            }
#pragma unroll
            for (int ns = 0; ns < 4; ns++) {
                int n  = wn + ns * 8 + (lane >> 2);
                int ck = kk + (lane & 3);
                bf[ns][0] = f2tf32(Bs[buf][n][ck]);
                bf[ns][1] = f2tf32(Bs[buf][n][ck + 4]);
            }
#pragma unroll
            for (int ns = 0; ns < 4; ns++)
                mma_tf32(acc[ns], af, bf[ns]);
        }
        __syncthreads();
    }

    // epilogue: scatter to out[b*DIM + i]
    const int rA = wm + (lane >> 2);
    const int b0 = s_ord[rA];
    const int b1 = s_ord[rA + 8];
#pragma unroll
    for (int ns = 0; ns < 4; ns++) {
        int c0 = i0 + wn + ns * 8 + 2 * (lane & 3);
        if (b0 >= 0)
            *(float2*)(out + (size_t)b0 * DIM + c0) = make_float2(acc[ns][0], acc[ns][1]);
        if (b1 >= 0)
            *(float2*)(out + (size_t)b1 * DIM + c0) = make_float2(acc[ns][2], acc[ns][3]);
    }
}

// ---------------- launch ----------------
extern "C" void kernel_launch(void* const* d_in, const int* in_sizes, int n_in,
                              void* d_out, int out_size)
{
    const float* pre = (const float*)d_in[0];
    const float* eff = (const float*)d_in[1];
    const int*   act = (const int*)d_in[2];
    const float* Wp  = (const float*)d_in[3];
    const float* bp  = (const float*)d_in[4];
    const float* We  = (const float*)d_in[5];
    const float* be  = (const float*)d_in[6];
    const float* Wt  = (const float*)d_in[7];

    float* out   = (float*)d_out;              // p_transformed: (B,1,DIM,1)
    float* out_e = out + (size_t)B_SZ * DIM;   // e_embed: (B,DIM)

    cudaFuncSetAttribute(embed_gemm, cudaFuncAttributeMaxDynamicSharedMemorySize, G1_SMEM);

    group_k<<<1, B_SZ>>>(act);

    mean_kernel<<<dim3(B_SZ * IN_DIM / 4 / 256, 2), 256>>>(pre, eff);

    embed_gemm<<<dim3(DIM / G1_BN, DIM / G1_BM, 2), 256, G1_SMEM>>>(Wp, bp, We, be, out_e);

    trans_gemm<<<dim3(DIM / T_BN, NACT, B_SZ / T_BM), 256>>>(Wt, out);
}